// round 1
// baseline (speedup 1.0000x reference)
#include <cuda_runtime.h>
#include <math.h>

// Problem constants
static constexpr int Bz   = 32;    // batch
static constexpr int INC  = 64;    // input channels
static constexpr int HIDN = 128;   // hidden
static constexpr int Gg   = 384;   // 3*HIDN gates
static constexpr int RR   = 63;    // active grid rows/cols (H-1, W-1)
static constexpr int CELLS = RR * RR; // 3969

// Scratch (allocation-free: __device__ globals)
__device__ float g_gx[(size_t)4 * CELLS * Bz * Gg];    // gx = x@Wx + b, scan-coord layout [d][p][q][b][g]
__device__ float g_h [(size_t)4 * CELLS * Bz * HIDN];  // hidden states,   layout [d][p][q][b][k]

// ---------------------------------------------------------------------------
__global__ void fill_ones_kernel(float4* out, int n4) {
    int i = blockIdx.x * 256 + threadIdx.x;
    if (i < n4) out[i] = make_float4(1.f, 1.f, 1.f, 1.f);
}

// ---------------------------------------------------------------------------
// gx[d][p][q][b][g] = sum_c x[b][c][ix][jx] * Wx[d][c][g] + bias[d][g]
// One CTA per (cell, d). 256 threads, thread tile = 2(b) x 24(g), K=64.
__global__ void gx_kernel(const float* __restrict__ x,
                          const float* __restrict__ Wx,
                          const float* __restrict__ bias) {
    __shared__ float Xs[INC * 33];   // [c][b], padded
    __shared__ float Ws[16 * Gg];

    const int cell = blockIdx.x;     // p*63 + q
    const int d    = blockIdx.y;
    const int p = cell / RR, q = cell % RR;
    const int ix = (d & 1) ? (62 - p) : p;   // fy flips rows
    const int jx = (d & 2) ? (62 - q) : q;   // fx flips cols
    const int t = threadIdx.x;

    // gather x[b][c][ix][jx] -> Xs[c][b]
    for (int m = t; m < Bz * INC; m += 256) {
        int b_ = m >> 6, c = m & 63;
        Xs[c * 33 + b_] = x[((size_t)(b_ * INC + c) << 12) + (ix << 6) + jx];
    }

    const int tx = t & 15, ty = t >> 4;
    const int g0 = tx * 24, b0 = ty * 2;

    float acc0[24], acc1[24];
    const float* bb = bias + d * Gg + g0;
#pragma unroll
    for (int j = 0; j < 24; j++) { float bv = bb[j]; acc0[j] = bv; acc1[j] = bv; }

    const float* Wd = Wx + (size_t)d * INC * Gg;
    for (int kb = 0; kb < INC; kb += 16) {
        __syncthreads();
        const float4* src = (const float4*)(Wd + (size_t)kb * Gg);
        float4* dst = (float4*)Ws;
        for (int f = t; f < 16 * Gg / 4; f += 256) dst[f] = src[f];
        __syncthreads();
#pragma unroll
        for (int kk = 0; kk < 16; kk++) {
            float a0 = Xs[(kb + kk) * 33 + b0];
            float a1 = Xs[(kb + kk) * 33 + b0 + 1];
            const float* wr = Ws + kk * Gg + g0;
#pragma unroll
            for (int j = 0; j < 24; j++) {
                float w = wr[j];
                acc0[j] += a0 * w;
                acc1[j] += a1 * w;
            }
        }
    }

    size_t base = ((size_t)(d * CELLS + cell) * Bz + b0) * Gg + g0;
#pragma unroll
    for (int j = 0; j < 24; j += 4) {
        *(float4*)(g_gx + base + j)      = make_float4(acc0[j], acc0[j+1], acc0[j+2], acc0[j+3]);
        *(float4*)(g_gx + base + Gg + j) = make_float4(acc1[j], acc1[j+1], acc1[j+2], acc1[j+3]);
    }
}

// ---------------------------------------------------------------------------
// One CTA per (cell on diagonal s, d).
// C[32][384] = gx + [h_up|h_left](32x256) @ [Wh;Wh2](256x384), then GRU epilogue.
// Dynamic smem: As 256*33, Ws 16*384, Cs 32*384 floats = 107520 B.
static constexpr int SCAN_SMEM = (256 * 33 + 16 * Gg + Bz * Gg) * 4;

__global__ void scan_kernel(const float* __restrict__ Wh,
                            const float* __restrict__ Wh2,
                            float* __restrict__ out,
                            int s, int qlo) {
    extern __shared__ float sm[];
    float* As = sm;                    // [k'(0..255)][b], padded stride 33
    float* Ws = As + 256 * 33;         // [kk][g]
    float* Cs = Ws + 16 * Gg;          // [b][g]

    const int d = blockIdx.y;
    const int q = qlo + blockIdx.x;
    const int p = s - q;
    const int t = threadIdx.x;
    const size_t cell = (size_t)d * CELLS + (size_t)p * RR + q;

    const float* hup = (p > 0) ? (g_h + ((size_t)d * CELLS + (size_t)(p - 1) * RR + q) * Bz * HIDN) : nullptr;
    const float* hlf = (q > 0) ? (g_h + ((size_t)d * CELLS + (size_t)p * RR + (q - 1)) * Bz * HIDN) : nullptr;

    // load A = [h_up ; h_left] transposed into As[k'][b]
    for (int m = t; m < Bz * HIDN; m += 256) {
        int b_ = m >> 7, k = m & 127;
        As[k * 33 + b_]         = hup ? hup[m] : 0.f;
        As[(128 + k) * 33 + b_] = hlf ? hlf[m] : 0.f;
    }

    const int tx = t & 15, ty = t >> 4;
    const int g0 = tx * 24, b0 = ty * 2;

    // acc init from gx
    const float* gxp = g_gx + (cell * Bz + b0) * Gg + g0;
    float acc0[24], acc1[24];
#pragma unroll
    for (int j = 0; j < 24; j++) { acc0[j] = gxp[j]; acc1[j] = gxp[Gg + j]; }

    const float* WhD  = Wh  + (size_t)d * HIDN * Gg;
    const float* Wh2D = Wh2 + (size_t)d * HIDN * Gg;

    for (int kb = 0; kb < 256; kb += 16) {
        __syncthreads();
        const float* srcf = (kb < 128) ? (WhD + (size_t)kb * Gg) : (Wh2D + (size_t)(kb - 128) * Gg);
        const float4* src = (const float4*)srcf;
        float4* dst = (float4*)Ws;
        for (int f = t; f < 16 * Gg / 4; f += 256) dst[f] = src[f];
        __syncthreads();
#pragma unroll
        for (int kk = 0; kk < 16; kk++) {
            float a0 = As[(kb + kk) * 33 + b0];
            float a1 = As[(kb + kk) * 33 + b0 + 1];
            const float* wr = Ws + kk * Gg + g0;
#pragma unroll
            for (int j = 0; j < 24; j++) {
                float w = wr[j];
                acc0[j] += a0 * w;
                acc1[j] += a1 * w;
            }
        }
    }

    // stash pre-activation sums in Cs
    {
        float* c0 = Cs + (size_t)b0 * Gg + g0;
#pragma unroll
        for (int j = 0; j < 24; j += 4) {
            *(float4*)(c0 + j)      = make_float4(acc0[j], acc0[j+1], acc0[j+2], acc0[j+3]);
            *(float4*)(c0 + Gg + j) = make_float4(acc1[j], acc1[j+1], acc1[j+2], acc1[j+3]);
        }
    }
    __syncthreads();

    // GRU epilogue
    const int oi = (d & 1) ? (63 - p) : p;
    const int oj = (d & 2) ? (63 - q) : q;
    float* hout = g_h + cell * Bz * HIDN;
    const float* gxn = g_gx + cell * Bz * Gg;

    for (int m = t; m < Bz * HIDN; m += 256) {
        int b_ = m >> 7, k = m & 127;
        float cr = Cs[(size_t)b_ * Gg + k];
        float cz = Cs[(size_t)b_ * Gg + 128 + k];
        float cn = Cs[(size_t)b_ * Gg + 256 + k];
        float gn = gxn[(size_t)b_ * Gg + 256 + k];        // gx_n (was folded into cn)
        float r  = 1.f / (1.f + expf(-cr));
        float z  = 1.f / (1.f + expf(-cz));
        float nn = tanhf(gn + r * (cn - gn));
        float hu = As[k * 33 + b_];
        float hl = As[(128 + k) * 33 + b_];
        float h  = (1.f - z) * nn + z * 0.5f * (hu + hl);
        hout[m] = h;
        out[((size_t)m * 4 + d) * 4096 + oi * 64 + oj] = h;   // (b,k,d,i,j)
    }
}

// ---------------------------------------------------------------------------
extern "C" void kernel_launch(void* const* d_in, const int* in_sizes, int n_in,
                              void* d_out, int out_size) {
    const float* x    = (const float*)d_in[0];
    const float* Wx   = (const float*)d_in[1];
    const float* Wh   = (const float*)d_in[2];
    const float* Wh2  = (const float*)d_in[3];
    const float* bias = (const float*)d_in[4];
    float* out = (float*)d_out;

    cudaFuncSetAttribute(scan_kernel, cudaFuncAttributeMaxDynamicSharedMemorySize, SCAN_SMEM);

    // 1) fill output with ones (uncomputed cells stay 1.0)
    int n4 = out_size / 4;
    fill_ones_kernel<<<(n4 + 255) / 256, 256>>>((float4*)d_out, n4);

    // 2) precompute gx for all directions/cells
    {
        dim3 grid(CELLS, 4);
        gx_kernel<<<grid, 256>>>(x, Wx, bias);
    }

    // 3) wavefront over anti-diagonals; inter-launch ordering supplies the dependency
    for (int s = 0; s < 2 * RR - 1; s++) {
        int qlo = (s - (RR - 1) > 0) ? (s - (RR - 1)) : 0;
        int qhi = (s < RR - 1) ? s : (RR - 1);
        int nq = qhi - qlo + 1;
        dim3 grid(nq, 4);
        scan_kernel<<<grid, 256, SCAN_SMEM>>>(Wh, Wh2, out, s, qlo);
    }
}

// round 3
// speedup vs baseline: 2.3959x; 2.3959x over previous
#include <cuda_runtime.h>
#include <math.h>

// Problem constants
static constexpr int Bz   = 32;    // batch
static constexpr int INC  = 64;    // input channels
static constexpr int HIDN = 128;   // hidden
static constexpr int Gg   = 384;   // 3*HIDN gates
static constexpr int RR   = 63;    // active grid rows/cols (H-1, W-1)
static constexpr int CELLS = RR * RR; // 3969

// Scratch (allocation-free: __device__ globals)
__device__ float g_gx[(size_t)4 * CELLS * Bz * Gg];    // gx = x@Wx + b   [d][p][q][b][g]
__device__ float g_h [(size_t)4 * CELLS * Bz * HIDN];  // hidden states  [d][p][q][b][k]

// ---------------------------------------------------------------------------
__device__ __forceinline__ unsigned smem_u32(const void* p) {
    return (unsigned)__cvta_generic_to_shared(p);
}
#define CPA16(dst, src) asm volatile("cp.async.cg.shared.global [%0], [%1], 16;" :: "r"(dst), "l"(src))
#define CPC()  asm volatile("cp.async.commit_group;")
#define CPW1() asm volatile("cp.async.wait_group 1;")
#define CPW0() asm volatile("cp.async.wait_group 0;")

__device__ __forceinline__ float sigf(float x)  { return 1.f / (1.f + __expf(-x)); }
__device__ __forceinline__ float tanhf_fast(float x) {
    float e = __expf(2.f * x);
    return (e - 1.f) / (e + 1.f);
}

// ---------------------------------------------------------------------------
__global__ void fill_ones_kernel(float4* out, int n4) {
    int i = blockIdx.x * 256 + threadIdx.x;
    if (i < n4) out[i] = make_float4(1.f, 1.f, 1.f, 1.f);
}

// ---------------------------------------------------------------------------
// gx[d][cell][b][g] = sum_c x[b][c][ix][jx] * Wx[d][c][g] + bias[d][g]
// One CTA per (cell,d). 256 threads. Thread tile: 2 b x 24 g (6 chunks of 4,
// chunk c at g = c*64 + tx*4 -> warp reads 256B contiguous, conflict-free).
static constexpr int GX_SMEM = (32 * 68 + 2 * 16 * Gg) * 4;  // 57856 B

__global__ void __launch_bounds__(256) gx_kernel(const float* __restrict__ x,
                                                 const float* __restrict__ Wx,
                                                 const float* __restrict__ bias) {
    extern __shared__ float sm[];
    float* Xs  = sm;             // [32][68]  x values [b][c]
    float* Wsb = sm + 32 * 68;   // [2][16][384] double-buffered weight blocks

    const int cellpq = blockIdx.x;
    const int d      = blockIdx.y;
    const int p = cellpq / RR, q = cellpq % RR;
    const int ix = (d & 1) ? (62 - p) : p;
    const int jx = (d & 2) ? (62 - q) : q;
    const int t = threadIdx.x;
    const int tx = t & 15, ty = t >> 4;
    const int b0 = ty * 2;
    const float* Wd = Wx + (size_t)d * INC * Gg;

    // stage weight block kb into buffer buf (16 rows x 384 cols)
    auto stageW = [&](int kb, int buf) {
        float* W = Wsb + buf * (16 * Gg);
        for (int f = t; f < 16 * 96; f += 256) {    // 96 x 16B chunks per row
            int kk = f / 96, x16 = f % 96;
            CPA16(smem_u32(W + kk * Gg + x16 * 4),
                  Wd + (size_t)(kb * 16 + kk) * Gg + x16 * 4);
        }
    };
    stageW(0, 0); CPC();
    stageW(1, 1); CPC();

    // gather x into Xs[b][c]  (plain ld/st, covered by __syncthreads)
    for (int m = t; m < Bz * INC; m += 256) {
        int b_ = m >> 6, c = m & 63;
        Xs[b_ * 68 + c] = x[((size_t)(b_ * INC + c) << 12) + (ix << 6) + jx];
    }

    // acc init from bias
    float acc[6][4][2];
    const float* bb = bias + d * Gg;
#pragma unroll
    for (int c = 0; c < 6; c++) {
        float4 v = *(const float4*)(bb + c * 64 + tx * 4);
        acc[c][0][0] = v.x; acc[c][0][1] = v.x;
        acc[c][1][0] = v.y; acc[c][1][1] = v.y;
        acc[c][2][0] = v.z; acc[c][2][1] = v.z;
        acc[c][3][0] = v.w; acc[c][3][1] = v.w;
    }

#pragma unroll 1
    for (int kb = 0; kb < 4; kb++) {
        if (kb < 3) { CPW1(); } else { CPW0(); }
        __syncthreads();
        const float* W = Wsb + (kb & 1) * (16 * Gg);
        const float* Arow = Xs + b0 * 68 + kb * 16;
#pragma unroll 8
        for (int kk = 0; kk < 16; kk++) {
            float a0 = Arow[kk];
            float a1 = Arow[68 + kk];
            const float* wr = W + kk * Gg + tx * 4;
#pragma unroll
            for (int c = 0; c < 6; c++) {
                float4 w = *(const float4*)(wr + c * 64);
                acc[c][0][0] += a0 * w.x; acc[c][0][1] += a1 * w.x;
                acc[c][1][0] += a0 * w.y; acc[c][1][1] += a1 * w.y;
                acc[c][2][0] += a0 * w.z; acc[c][2][1] += a1 * w.z;
                acc[c][3][0] += a0 * w.w; acc[c][3][1] += a1 * w.w;
            }
        }
        __syncthreads();
        if (kb < 2) { stageW(kb + 2, kb & 1); CPC(); }
    }

    // store gx
    float* gp = g_gx + ((size_t)(d * CELLS + cellpq) * Bz + b0) * Gg;
#pragma unroll
    for (int c = 0; c < 6; c++) {
#pragma unroll
        for (int b2 = 0; b2 < 2; b2++) {
            *(float4*)(gp + (size_t)b2 * Gg + c * 64 + tx * 4) =
                make_float4(acc[c][0][b2], acc[c][1][b2], acc[c][2][b2], acc[c][3][b2]);
        }
    }
}

// ---------------------------------------------------------------------------
// scan: one CTA per (cell-on-diagonal, k-half, d).
// CTA owns k in [k0, k0+64) -> 192 gate cols {gate*128 + k0..k0+63}.
// C[g][b] = gx + sum_k' Wrow[g][k'] * A[k'][b], K=256 ([h_up | h_left]).
// Thread (tx,ty): b = {2ty, 2ty+1}; 3 chunks of 4 cols, chunk g at
// tile col gate*64 + tx*4 (k = k0 + tx*4) -> complete (r,z,n) quadruples
// per thread -> all-register GRU epilogue. Conflict-free 256B warp reads.
static constexpr int SCAN_SMEM = (2 * 32 * 132 + 2 * 16 * 192) * 4;  // 58368 B

__global__ void __launch_bounds__(256) scan_kernel(const float* __restrict__ Wh,
                                                   const float* __restrict__ Wh2,
                                                   float* __restrict__ out,
                                                   int s, int qlo) {
    extern __shared__ float sm[];
    float* Aup = sm;                 // [32][132]  h_up  [b][k]
    float* Alf = sm + 32 * 132;      // [32][132]  h_left[b][k]
    float* Wsb = sm + 2 * 32 * 132;  // [2][16][192] weight blocks

    const int d  = blockIdx.y;
    const int bx = blockIdx.x;
    const int q  = qlo + (bx >> 1);
    const int p  = s - q;
    const int k0 = (bx & 1) * 64;
    const int t  = threadIdx.x;
    const int tx = t & 15, ty = t >> 4;
    const int b0 = ty * 2;
    const size_t cell = (size_t)d * CELLS + (size_t)p * RR + q;

    const float* hup = (p > 0) ? g_h + (cell - RR) * (Bz * HIDN) : nullptr;
    const float* hlf = (q > 0) ? g_h + (cell - 1)  * (Bz * HIDN) : nullptr;

    // stage A (h_up, h_left); issued BEFORE first commit so it lands in group 0
    for (int f = t; f < 1024; f += 256) {
        int b_ = f >> 5, c16 = f & 31;
        float* du = Aup + b_ * 132 + c16 * 4;
        float* dl = Alf + b_ * 132 + c16 * 4;
        if (hup) { CPA16(smem_u32(du), hup + b_ * 128 + c16 * 4); }
        else     { *(float4*)du = make_float4(0.f, 0.f, 0.f, 0.f); }
        if (hlf) { CPA16(smem_u32(dl), hlf + b_ * 128 + c16 * 4); }
        else     { *(float4*)dl = make_float4(0.f, 0.f, 0.f, 0.f); }
    }

    const float* WhD  = Wh  + (size_t)d * HIDN * Gg;
    const float* Wh2D = Wh2 + (size_t)d * HIDN * Gg;

    // stage weight block kb (16 k-rows x 192 needed cols) into buffer buf.
    // tile col layout: gate*64 + (k - k0); global col: gate*128 + k.
    auto stageW = [&](int kb, int buf) {
        float* W = Wsb + buf * (16 * 192);
        for (int f = t; f < 768; f += 256) {         // 48 x 16B chunks per row
            int kk = f / 48, ch = f % 48;
            int gate = ch >> 4, x = ch & 15;
            int kg = kb * 16 + kk;
            const float* src = (kg < 128 ? WhD + (size_t)kg * Gg
                                         : Wh2D + (size_t)(kg - 128) * Gg)
                               + gate * 128 + k0 + x * 4;
            CPA16(smem_u32(W + kk * 192 + gate * 64 + x * 4), src);
        }
    };
    stageW(0, 0); CPC();   // group 0 = A + W-block 0
    stageW(1, 1); CPC();   // group 1 = W-block 1

    // acc init: r,z gates from gx; n gate accumulates pure recurrent sum
    float acc[3][4][2];            // [gate][jj][b2]
    const float* gxp = g_gx + (cell * Bz) * Gg;
    const int kth = k0 + tx * 4;   // this thread's k (0..124)
#pragma unroll
    for (int b2 = 0; b2 < 2; b2++) {
        const float* gp = gxp + (size_t)(b0 + b2) * Gg + kth;
        float4 vr = *(const float4*)(gp);
        float4 vz = *(const float4*)(gp + 128);
        acc[0][0][b2] = vr.x; acc[0][1][b2] = vr.y;
        acc[0][2][b2] = vr.z; acc[0][3][b2] = vr.w;
        acc[1][0][b2] = vz.x; acc[1][1][b2] = vz.y;
        acc[1][2][b2] = vz.z; acc[1][3][b2] = vz.w;
        acc[2][0][b2] = 0.f;  acc[2][1][b2] = 0.f;
        acc[2][2][b2] = 0.f;  acc[2][3][b2] = 0.f;
    }

#pragma unroll 1
    for (int kb = 0; kb < 16; kb++) {
        if (kb < 15) { CPW1(); } else { CPW0(); }
        __syncthreads();
        const float* W = Wsb + (kb & 1) * (16 * 192);
        const float* Arow = (kb < 8) ? (Aup + b0 * 132 + kb * 16)
                                     : (Alf + b0 * 132 + (kb - 8) * 16);
#pragma unroll 8
        for (int kk = 0; kk < 16; kk++) {
            float a0 = Arow[kk];
            float a1 = Arow[132 + kk];
            const float* wr = W + kk * 192 + tx * 4;
#pragma unroll
            for (int gate = 0; gate < 3; gate++) {
                float4 w = *(const float4*)(wr + gate * 64);
                acc[gate][0][0] += a0 * w.x; acc[gate][0][1] += a1 * w.x;
                acc[gate][1][0] += a0 * w.y; acc[gate][1][1] += a1 * w.y;
                acc[gate][2][0] += a0 * w.z; acc[gate][2][1] += a1 * w.z;
                acc[gate][3][0] += a0 * w.w; acc[gate][3][1] += a1 * w.w;
            }
        }
        __syncthreads();
        if (kb < 14) { stageW(kb + 2, kb & 1); CPC(); }
    }

    // GRU epilogue, all in registers
    const int oi = (d & 1) ? (63 - p) : p;
    const int oj = (d & 2) ? (63 - q) : q;
    float* hptr = g_h + cell * (Bz * HIDN);
    const int k = kth;

#pragma unroll
    for (int b2 = 0; b2 < 2; b2++) {
        int b = b0 + b2;
        float4 gn = *(const float4*)(gxp + (size_t)b * Gg + 256 + k);
        float4 hu = *(const float4*)(Aup + b * 132 + k);
        float4 hl = *(const float4*)(Alf + b * 132 + k);
        float4 h;
        {
            float r = sigf(acc[0][0][b2]);
            float z = sigf(acc[1][0][b2]);
            float nn = tanhf_fast(gn.x + r * acc[2][0][b2]);
            h.x = (1.f - z) * nn + z * 0.5f * (hu.x + hl.x);
        }
        {
            float r = sigf(acc[0][1][b2]);
            float z = sigf(acc[1][1][b2]);
            float nn = tanhf_fast(gn.y + r * acc[2][1][b2]);
            h.y = (1.f - z) * nn + z * 0.5f * (hu.y + hl.y);
        }
        {
            float r = sigf(acc[0][2][b2]);
            float z = sigf(acc[1][2][b2]);
            float nn = tanhf_fast(gn.z + r * acc[2][2][b2]);
            h.z = (1.f - z) * nn + z * 0.5f * (hu.z + hl.z);
        }
        {
            float r = sigf(acc[0][3][b2]);
            float z = sigf(acc[1][3][b2]);
            float nn = tanhf_fast(gn.w + r * acc[2][3][b2]);
            h.w = (1.f - z) * nn + z * 0.5f * (hu.w + hl.w);
        }
        *(float4*)(hptr + b * 128 + k) = h;
        size_t ob = ((size_t)(b * 128 + k) * 4 + d) * 4096 + (size_t)oi * 64 + oj;
        out[ob]             = h.x;
        out[ob + 4  * 4096] = h.y;
        out[ob + 8  * 4096] = h.z;
        out[ob + 12 * 4096] = h.w;
    }
}

// ---------------------------------------------------------------------------
extern "C" void kernel_launch(void* const* d_in, const int* in_sizes, int n_in,
                              void* d_out, int out_size) {
    const float* x    = (const float*)d_in[0];
    const float* Wx   = (const float*)d_in[1];
    const float* Wh   = (const float*)d_in[2];
    const float* Wh2  = (const float*)d_in[3];
    const float* bias = (const float*)d_in[4];
    float* out = (float*)d_out;

    cudaFuncSetAttribute(scan_kernel, cudaFuncAttributeMaxDynamicSharedMemorySize, SCAN_SMEM);
    cudaFuncSetAttribute(gx_kernel,   cudaFuncAttributeMaxDynamicSharedMemorySize, GX_SMEM);

    // 1) fill output with ones (uncomputed border cells stay 1.0)
    int n4 = out_size / 4;
    fill_ones_kernel<<<(n4 + 255) / 256, 256>>>((float4*)d_out, n4);

    // 2) precompute gx for all directions/cells
    {
        dim3 grid(CELLS, 4);
        gx_kernel<<<grid, 256, GX_SMEM>>>(x, Wx, bias);
    }

    // 3) wavefront over anti-diagonals; 2 CTAs per cell (k-halves)
    for (int s = 0; s < 2 * RR - 1; s++) {
        int qlo = (s - (RR - 1) > 0) ? (s - (RR - 1)) : 0;
        int qhi = (s < RR - 1) ? s : (RR - 1);
        int nq = qhi - qlo + 1;
        dim3 grid(2 * nq, 4);
        scan_kernel<<<grid, 256, SCAN_SMEM>>>(Wh, Wh2, out, s, qlo);
    }
}